// round 4
// baseline (speedup 1.0000x reference)
#include <cuda_runtime.h>
#include <cstdint>

#define H 128
#define W 128
#define OH 64
#define OW 64
#define TAPS 6
#define NTHREADS 256

// Dynamic SMEM layout (floats unless noted):
//   xs   [128*128]      input tile
//   tmp  [64*128]       row-resized intermediate
//   wh   [64*6]         row-resize taps
//   ww   [64*6]         col-resize taps
//   hb   [64] (int)     row tap base index
//   wb   [64] (int)     col tap base index
//   red  [32]           max-reduction scratch (red[0] reused as thr)
//   bbox [4]            lo_h, hi_h, lo_w, hi_w (floats, as in reference)
//   flags[768 bytes]    rowBelow[128] rowTable[128] colBelowA/B colTableA/B
#define XS_F      (H*W)
#define TMP_F     (OH*W)
#define WH_F      (OH*TAPS)
#define WW_F      (OW*TAPS)
#define SMEM_FLOATS (XS_F + TMP_F + WH_F + WW_F)
#define SMEM_BYTES  (SMEM_FLOATS*4 + 64*4*2 /*hb,wb*/ + 32*4 /*red*/ + 4*4 /*bbox*/ + 768 /*flags*/)

__global__ void __launch_bounds__(NTHREADS, 2)
smartpool_kernel(const float* __restrict__ x, float* __restrict__ out)
{
    extern __shared__ float sm[];
    float* xs   = sm;
    float* tmp  = xs + XS_F;
    float* wh   = tmp + TMP_F;
    float* ww   = wh + WH_F;
    int*   hb   = (int*)(ww + WW_F);
    int*   wb   = hb + OH;
    float* red  = (float*)(wb + OW);
    float* bbox = red + 32;
    unsigned char* rowBelow = (unsigned char*)(bbox + 4);
    unsigned char* rowTable = rowBelow + 128;
    unsigned char* colBelowA = rowTable + 128;
    unsigned char* colTableA = colBelowA + 128;
    unsigned char* colBelowB = colTableA + 128;
    unsigned char* colTableB = colBelowB + 128;

    const int nc  = blockIdx.x;
    const int tid = threadIdx.x;
    const int lane = tid & 31;
    const int wi   = tid >> 5;

    const float* xc = x + (size_t)nc * (H * W);

    // ---------------- Phase 1: load tile (float4) + per-thread max ----------
    float vmax = -3.402823466e38f;
    const float4* x4  = (const float4*)xc;
    float4*       xs4 = (float4*)xs;
    #pragma unroll
    for (int i = 0; i < (H*W/4)/NTHREADS; i++) {
        int idx = tid + i * NTHREADS;
        float4 v = x4[idx];
        xs4[idx] = v;
        vmax = fmaxf(vmax, fmaxf(fmaxf(v.x, v.y), fmaxf(v.z, v.w)));
    }
    #pragma unroll
    for (int o = 16; o; o >>= 1)
        vmax = fmaxf(vmax, __shfl_xor_sync(0xFFFFFFFFu, vmax, o));
    if (lane == 0) red[wi] = vmax;
    __syncthreads();
    if (tid == 0) {
        float m = red[0];
        #pragma unroll
        for (int i = 1; i < NTHREADS/32; i++) m = fmaxf(m, red[i]);
        red[0] = 0.1f * m;   // thr = RATIO * max
    }
    __syncthreads();
    const float thr = red[0];

    // ---------------- Phase 2: row flags (warp-ballot) + col flags ----------
    // Rows: warp wi handles rows [wi*16, wi*16+16). Lanes stride the columns.
    {
        const int r0 = wi * (H / (NTHREADS/32));
        for (int r = r0; r < r0 + (H / (NTHREADS/32)); r++) {
            const float* row = xs + r * W;
            bool below = false, tab = false;
            #pragma unroll
            for (int k = 0; k < W/32; k++) {
                float v = row[lane + 32*k];
                below |= (v <  thr);
                tab   |= (v >= thr);
            }
            unsigned bb = __ballot_sync(0xFFFFFFFFu, below);
            unsigned tb = __ballot_sync(0xFFFFFFFFu, tab);
            if (lane == 0) { rowBelow[r] = (bb != 0); rowTable[r] = (tb != 0); }
        }
    }
    // Cols: thread t<128 scans rows 0..63 of col t; t>=128 scans rows 64..127.
    {
        const int c = tid & 127;
        const int rbase = (tid >> 7) * 64;
        bool below = false, tab = false;
        #pragma unroll 8
        for (int r = rbase; r < rbase + 64; r++) {
            float v = xs[r * W + c];
            below |= (v <  thr);
            tab   |= (v >= thr);
        }
        if (tid < 128) { colBelowA[c] = below; colTableA[c] = tab; }
        else           { colBelowB[c] = below; colTableB[c] = tab; }
    }
    __syncthreads();

    // ---------------- Phase 3: bbox reduce (warp 0 rows, warp 1 cols) -------
    if (wi == 0) {
        bool orB = false; int mx = 0;
        #pragma unroll
        for (int k = lane; k < 128; k += 32) {
            if (k >= 1) {
                orB |= (rowBelow[k] != 0);
                if (rowTable[k]) mx = max(mx, k);
            }
        }
        orB = __any_sync(0xFFFFFFFFu, orB);
        #pragma unroll
        for (int o = 16; o; o >>= 1) mx = max(mx, __shfl_xor_sync(0xFFFFFFFFu, mx, o));
        if (lane == 0) { bbox[0] = orB ? 0.0f : 1.0f; bbox[1] = (float)mx; }
    } else if (wi == 1) {
        bool orB = false; int mx = 0;
        #pragma unroll
        for (int k = lane; k < 128; k += 32) {
            if (k >= 1) {
                orB |= (colBelowA[k] != 0) || (colBelowB[k] != 0);
                if (colTableA[k] || colTableB[k]) mx = max(mx, k);
            }
        }
        orB = __any_sync(0xFFFFFFFFu, orB);
        #pragma unroll
        for (int o = 16; o; o >>= 1) mx = max(mx, __shfl_xor_sync(0xFFFFFFFFu, mx, o));
        if (lane == 0) { bbox[2] = orB ? 0.0f : 1.0f; bbox[3] = (float)mx; }
    }
    __syncthreads();

    // ---------------- Phase 4: 6-tap antialiased-bilinear weights -----------
    // tid<64 -> Wh row o=tid; tid in [64,128) -> Ww row o=tid-64.
    if (tid < 128) {
        const int isW = tid >> 6;
        const int o   = tid & 63;
        const float lo = bbox[isW * 2 + 0];
        const float hi = bbox[isW * 2 + 1];
        const float L       = hi - lo + 1.0f;
        const float scale   = L * (1.0f / 64.0f);
        const float support = fmaxf(scale, 1.0f);
        const float center  = scale * ((float)o + 0.5f);
        const float a       = lo - 0.5f + center;          // peak position in j
        const int   j0      = (int)floorf(a - support);
        float wloc[TAPS];
        float ssum = 0.0f;
        #pragma unroll
        for (int k = 0; k < TAPS; k++) {
            float jf = (float)(j0 + k);
            float wv = fmaxf(0.0f, 1.0f - fabsf(jf - a) / support);
            wv = (jf >= lo && jf <= hi) ? wv : 0.0f;       // validity mask
            wloc[k] = wv;
            ssum += wv;
        }
        const float inv = 1.0f / fmaxf(ssum, 1e-12f);
        float* wdst = isW ? ww : wh;
        int*   bdst = isW ? wb : hb;
        #pragma unroll
        for (int k = 0; k < TAPS; k++) wdst[o * TAPS + k] = wloc[k] * inv;
        bdst[o] = j0;
    }
    __syncthreads();

    // ---------------- Phase 5: row resize  tmp[o][w] = sum_k wh*xs ----------
    #pragma unroll 4
    for (int e = tid; e < OH * W; e += NTHREADS) {
        const int o = e >> 7;
        const int w = e & 127;
        const int j0 = hb[o];
        float acc = 0.0f;
        #pragma unroll
        for (int k = 0; k < TAPS; k++) {
            int j = min(max(j0 + k, 0), H - 1);   // weight is 0 when clamped
            acc = fmaf(wh[o * TAPS + k], xs[j * W + w], acc);
        }
        tmp[e] = acc;
    }
    __syncthreads();

    // ---------------- Phase 6: col resize  out[o][p] = sum_k ww*tmp ---------
    float* outc = out + (size_t)nc * (OH * OW);
    #pragma unroll 4
    for (int e = tid; e < OH * OW; e += NTHREADS) {
        const int o = e >> 6;
        const int p = e & 63;
        const int j0 = wb[p];
        float acc = 0.0f;
        #pragma unroll
        for (int k = 0; k < TAPS; k++) {
            int j = min(max(j0 + k, 0), W - 1);
            acc = fmaf(ww[p * TAPS + k], tmp[o * W + j], acc);
        }
        outc[e] = acc;
    }
}

extern "C" void kernel_launch(void* const* d_in, const int* in_sizes, int n_in,
                              void* d_out, int out_size)
{
    const float* x = (const float*)d_in[0];
    float* out = (float*)d_out;
    const int nc = in_sizes[0] / (H * W);   // 32*128 = 4096 channels
    cudaFuncSetAttribute(smartpool_kernel,
                         cudaFuncAttributeMaxDynamicSharedMemorySize, SMEM_BYTES);
    smartpool_kernel<<<nc, NTHREADS, SMEM_BYTES>>>(x, out);
}

// round 5
// speedup vs baseline: 1.3078x; 1.3078x over previous
#include <cuda_runtime.h>
#include <cstdint>

#define H 128
#define W 128
#define OH 64
#define OW 64
#define TAPS 6
#define NTHREADS 256
#define NWARPS 8

// SMEM (floats): xs 16384 | tmp 8192 | wtab 768 | itab 768(int) |
//                rowMin 128 | rowMax 128 | misc 8
// Aliased onto tmp (dead before Phase 5 writes it):
//   partMin[8*128], partMax[8*128], colMin[128], colMax[128]
#define SMEM_FLOATS (16384 + 8192 + 768 + 768 + 128 + 128 + 8)
#define SMEM_BYTES  (SMEM_FLOATS * 4)

__global__ void __launch_bounds__(NTHREADS, 2)
smartpool_kernel(const float* __restrict__ x, float* __restrict__ out)
{
    extern __shared__ float sm[];
    float* xs     = sm;                       // [128][128]
    float* tmp    = xs + 16384;               // [64][128]
    float* wtab   = tmp + 8192;               // [2][64][6] weights
    int*   itab   = (int*)(wtab + 768);       // [2][64][6] precomputed indices
    float* rowMin = (float*)(itab + 768);     // [128]
    float* rowMax = rowMin + 128;             // [128]
    float* misc   = rowMax + 128;             // [0]=thr [1..2]=row bbox [3..4]=col bbox
    // aliases on tmp (used only before Phase 5)
    float* partMin = tmp;                     // [8][128]
    float* partMax = tmp + 1024;              // [8][128]
    float* colMin  = tmp + 2048;              // [128]
    float* colMax  = colMin + 128;            // [128]

    const int nc   = blockIdx.x;
    const int tid  = threadIdx.x;
    const int lane = tid & 31;
    const int wi   = tid >> 5;
    const unsigned FULL = 0xFFFFFFFFu;
    const float FINF = 3.402823466e38f;

    const float4* x4  = (const float4*)(x + (size_t)nc * (H * W));
    float4*       xs4 = (float4*)xs;
    float4*       tmp4 = (float4*)tmp;

    // ===== Phase 1: stream tile to SMEM, fused row/col min-max stats ========
    // idx = tid + 256*i  ->  row r = wi + 8*i (one full row per warp-iter),
    // lane's float4 covers fixed columns 4*lane..4*lane+3 every iteration.
    float4 cmn = {FINF, FINF, FINF, FINF};
    float4 cmx = {-FINF, -FINF, -FINF, -FINF};
    #pragma unroll
    for (int i = 0; i < 16; i++) {
        const int idx = tid + i * NTHREADS;
        const float4 v = x4[idx];
        xs4[idx] = v;
        // column partials (registers, fixed cols per lane)
        cmn.x = fminf(cmn.x, v.x); cmn.y = fminf(cmn.y, v.y);
        cmn.z = fminf(cmn.z, v.z); cmn.w = fminf(cmn.w, v.w);
        cmx.x = fmaxf(cmx.x, v.x); cmx.y = fmaxf(cmx.y, v.y);
        cmx.z = fmaxf(cmx.z, v.z); cmx.w = fmaxf(cmx.w, v.w);
        // row stats: warp covers the whole row this iteration
        float lmn = fminf(fminf(v.x, v.y), fminf(v.z, v.w));
        float lmx = fmaxf(fmaxf(v.x, v.y), fmaxf(v.z, v.w));
        #pragma unroll
        for (int o = 16; o; o >>= 1) {
            lmn = fminf(lmn, __shfl_xor_sync(FULL, lmn, o));
            lmx = fmaxf(lmx, __shfl_xor_sync(FULL, lmx, o));
        }
        if (lane == 0) {
            const int r = wi + 8 * i;
            rowMin[r] = lmn;
            rowMax[r] = lmx;
        }
    }
    ((float4*)partMin)[wi * 32 + lane] = cmn;
    ((float4*)partMax)[wi * 32 + lane] = cmx;
    __syncthreads();

    // ===== Phase 2: finish stats (col reduce warps 0-3, thr warp 4) ========
    if (tid < 128) {
        const int c = tid;
        float mn = partMin[c], mx = partMax[c];
        #pragma unroll
        for (int w = 1; w < 8; w++) {
            mn = fminf(mn, partMin[w * 128 + c]);
            mx = fmaxf(mx, partMax[w * 128 + c]);
        }
        colMin[c] = mn;
        colMax[c] = mx;
    } else if (wi == 4) {
        float m = fmaxf(fmaxf(rowMax[lane], rowMax[lane + 32]),
                        fmaxf(rowMax[lane + 64], rowMax[lane + 96]));
        #pragma unroll
        for (int o = 16; o; o >>= 1) m = fmaxf(m, __shfl_xor_sync(FULL, m, o));
        if (lane == 0) misc[0] = 0.1f * m;      // thr = RATIO * max
    }
    __syncthreads();
    const float thr = misc[0];

    // ===== Phase 3: bbox (warp 0 rows, warp 1 cols) =========================
    // x_min = 0 iff any index k>=1 has min<thr else 1; x_max = max{k>=1 : max>=thr} else 0
    if (wi == 0) {
        bool orB = false; int mx = 0;
        #pragma unroll
        for (int k = lane; k < 128; k += 32) {
            if (k >= 1) {
                if (rowMin[k] <  thr) orB = true;
                if (rowMax[k] >= thr) mx = max(mx, k);
            }
        }
        orB = __any_sync(FULL, orB);
        #pragma unroll
        for (int o = 16; o; o >>= 1) mx = max(mx, __shfl_xor_sync(FULL, mx, o));
        if (lane == 0) { misc[1] = orB ? 0.0f : 1.0f; misc[2] = (float)mx; }
    } else if (wi == 1) {
        bool orB = false; int mx = 0;
        #pragma unroll
        for (int k = lane; k < 128; k += 32) {
            if (k >= 1) {
                if (colMin[k] <  thr) orB = true;
                if (colMax[k] >= thr) mx = max(mx, k);
            }
        }
        orB = __any_sync(FULL, orB);
        #pragma unroll
        for (int o = 16; o; o >>= 1) mx = max(mx, __shfl_xor_sync(FULL, mx, o));
        if (lane == 0) { misc[3] = orB ? 0.0f : 1.0f; misc[4] = (float)mx; }
    }
    __syncthreads();

    // ===== Phase 4: weight + clamped-index tables ===========================
    if (tid < 128) {
        const int  isW = tid >> 6;
        const int  o   = tid & 63;
        const float lo = misc[1 + 2 * isW];
        const float hi = misc[2 + 2 * isW];
        const float L       = hi - lo + 1.0f;
        const float scale   = L * (1.0f / 64.0f);
        const float support = fmaxf(scale, 1.0f);
        const float a       = lo - 0.5f + scale * ((float)o + 0.5f);
        const int   j0      = (int)floorf(a - support);
        float wloc[TAPS]; float ssum = 0.0f;
        #pragma unroll
        for (int k = 0; k < TAPS; k++) {
            const float jf = (float)(j0 + k);
            float wv = fmaxf(0.0f, 1.0f - fabsf(jf - a) / support);
            wv = (jf >= lo && jf <= hi) ? wv : 0.0f;
            wloc[k] = wv; ssum += wv;
        }
        const float inv = 1.0f / fmaxf(ssum, 1e-12f);
        const int base = isW * 384 + o * 6;
        #pragma unroll
        for (int k = 0; k < TAPS; k++) {
            wtab[base + k] = wloc[k] * inv;
            const int j = min(max(j0 + k, 0), 127);        // weight 0 when clamped
            itab[base + k] = isW ? j : j * 32;             // P5: float4 row offset; P6: element
        }
    }
    __syncthreads();

    // ===== Phase 5: row resize, warp-per-output-row, float4 =================
    // tmp[o][w] = sum_k wh[o][k] * xs[jk][w]; lane handles 4 consecutive w.
    #pragma unroll
    for (int o = wi; o < OH; o += NWARPS) {
        const float* wp = wtab + o * 6;
        const int*   ip = itab + o * 6;
        const float w0 = wp[0], w1 = wp[1], w2 = wp[2],
                    w3 = wp[3], w4 = wp[4], w5 = wp[5];
        const float4 a0 = xs4[ip[0] + lane];
        const float4 a1 = xs4[ip[1] + lane];
        const float4 a2 = xs4[ip[2] + lane];
        const float4 a3 = xs4[ip[3] + lane];
        const float4 a4 = xs4[ip[4] + lane];
        const float4 a5 = xs4[ip[5] + lane];
        float4 acc;
        acc.x = fmaf(w5, a5.x, fmaf(w4, a4.x, fmaf(w3, a3.x, fmaf(w2, a2.x, fmaf(w1, a1.x, w0 * a0.x)))));
        acc.y = fmaf(w5, a5.y, fmaf(w4, a4.y, fmaf(w3, a3.y, fmaf(w2, a2.y, fmaf(w1, a1.y, w0 * a0.y)))));
        acc.z = fmaf(w5, a5.z, fmaf(w4, a4.z, fmaf(w3, a3.z, fmaf(w2, a2.z, fmaf(w1, a1.z, w0 * a0.z)))));
        acc.w = fmaf(w5, a5.w, fmaf(w4, a4.w, fmaf(w3, a3.w, fmaf(w2, a2.w, fmaf(w1, a1.w, w0 * a0.w)))));
        tmp4[o * 32 + lane] = acc;
    }
    __syncthreads();

    // ===== Phase 6: col resize ==============================================
    // out[o][p] = sum_k ww[p][k] * tmp[o][jk]; thread owns fixed p, 16 o's.
    {
        const int p  = tid & 63;
        const int og = tid >> 6;                 // uniform within a warp
        const float* wp = wtab + 384 + p * 6;
        const int*   ip = itab + 384 + p * 6;
        const float w0 = wp[0], w1 = wp[1], w2 = wp[2],
                    w3 = wp[3], w4 = wp[4], w5 = wp[5];
        const int j0 = ip[0], j1 = ip[1], j2 = ip[2],
                  j3 = ip[3], j4 = ip[4], j5 = ip[5];
        float* outc = out + (size_t)nc * (OH * OW);
        #pragma unroll
        for (int g = 0; g < 16; g++) {
            const int o = og * 16 + g;
            const float* tr = tmp + o * W;
            float acc;
            acc = fmaf(w5, tr[j5], fmaf(w4, tr[j4], fmaf(w3, tr[j3],
                  fmaf(w2, tr[j2], fmaf(w1, tr[j1], w0 * tr[j0])))));
            outc[o * OW + p] = acc;
        }
    }
}

extern "C" void kernel_launch(void* const* d_in, const int* in_sizes, int n_in,
                              void* d_out, int out_size)
{
    const float* x = (const float*)d_in[0];
    float* out = (float*)d_out;
    const int nc = in_sizes[0] / (H * W);   // 4096 channels
    cudaFuncSetAttribute(smartpool_kernel,
                         cudaFuncAttributeMaxDynamicSharedMemorySize, SMEM_BYTES);
    smartpool_kernel<<<nc, NTHREADS, SMEM_BYTES>>>(x, out);
}

// round 8
// speedup vs baseline: 1.5413x; 1.1786x over previous
#include <cuda_runtime.h>
#include <cuda_fp16.h>
#include <cstdint>

#define H 128
#define W 128
#define OH 64
#define OW 64
#define TAPS 6
#define NTHREADS 256
#define NWARPS 8

// SMEM bytes: xs fp16 32768 | tmp fp32 32768 | wtab 3072 | itab 3072 |
//             rowMin 512 | rowMax 512 | misc 32   => 72,736 B  (3 CTAs/SM)
// Aliased onto tmp (dead before Phase 5): partMin[8*128], partMax[8*128],
//             colMin[128], colMax[128] (all fp32)
#define SMEM_BYTES (32768 + 32768 + 3072 + 3072 + 512 + 512 + 32)

__global__ void __launch_bounds__(NTHREADS, 3)
smartpool_kernel(const float* __restrict__ x, float* __restrict__ out)
{
    extern __shared__ float sm[];
    uint2* xs2    = (uint2*)sm;               // [128 rows][32 uint2] = 4 halfs each
    float* tmp    = sm + 32768/4;             // [64][128] fp32
    float* wtab   = tmp + 8192;               // [2][64][6] weights
    int*   itab   = (int*)(wtab + 768);       // [2][64][6] precomputed indices
    float* rowMin = (float*)(itab + 768);     // [128]
    float* rowMax = rowMin + 128;             // [128]
    float* misc   = rowMax + 128;             // [0]=thr [1..2]=row bbox [3..4]=col bbox
    // aliases on tmp (used only before Phase 5)
    float* partMin = tmp;                     // [8][128]
    float* partMax = tmp + 1024;              // [8][128]
    float* colMin  = tmp + 2048;              // [128]
    float* colMax  = colMin + 128;            // [128]

    const int nc   = blockIdx.x;
    const int tid  = threadIdx.x;
    const int lane = tid & 31;
    const int wi   = tid >> 5;
    const unsigned FULL = 0xFFFFFFFFu;
    const float FINF = 3.402823466e38f;

    const float4* x4 = (const float4*)(x + (size_t)nc * (H * W));
    float4* tmp4 = (float4*)tmp;

    // ===== Phase 1: stream tile -> fp16 SMEM, fused row/col min-max stats ===
    // idx = tid + 256*i -> row r = wi + 8*i (warp covers the full row each iter),
    // lane's float4 covers fixed columns 4*lane..4*lane+3.
    float4 cmn = {FINF, FINF, FINF, FINF};
    float4 cmx = {-FINF, -FINF, -FINF, -FINF};
    #pragma unroll 8
    for (int i = 0; i < 16; i++) {
        const int idx = tid + i * NTHREADS;
        const float4 v = x4[idx];
        // fp16 store (resize input only; stats use exact fp32 below)
        __half2 h01 = __floats2half2_rn(v.x, v.y);
        __half2 h23 = __floats2half2_rn(v.z, v.w);
        uint2 pk;
        pk.x = *(const unsigned*)&h01;
        pk.y = *(const unsigned*)&h23;
        xs2[idx] = pk;
        // column partials (registers, fixed cols per lane)
        cmn.x = fminf(cmn.x, v.x); cmn.y = fminf(cmn.y, v.y);
        cmn.z = fminf(cmn.z, v.z); cmn.w = fminf(cmn.w, v.w);
        cmx.x = fmaxf(cmx.x, v.x); cmx.y = fmaxf(cmx.y, v.y);
        cmx.z = fmaxf(cmx.z, v.z); cmx.w = fmaxf(cmx.w, v.w);
        // row stats via warp reduce
        float lmn = fminf(fminf(v.x, v.y), fminf(v.z, v.w));
        float lmx = fmaxf(fmaxf(v.x, v.y), fmaxf(v.z, v.w));
        #pragma unroll
        for (int o = 16; o; o >>= 1) {
            lmn = fminf(lmn, __shfl_xor_sync(FULL, lmn, o));
            lmx = fmaxf(lmx, __shfl_xor_sync(FULL, lmx, o));
        }
        if (lane == 0) {
            const int r = wi + 8 * i;
            rowMin[r] = lmn;
            rowMax[r] = lmx;
        }
    }
    ((float4*)partMin)[wi * 32 + lane] = cmn;
    ((float4*)partMax)[wi * 32 + lane] = cmx;
    __syncthreads();

    // ===== Phase 2: finish stats (col reduce tids 0-127, thr warp 4) ========
    if (tid < 128) {
        const int c = tid;
        float mn = partMin[c], mx = partMax[c];
        #pragma unroll
        for (int w = 1; w < 8; w++) {
            mn = fminf(mn, partMin[w * 128 + c]);
            mx = fmaxf(mx, partMax[w * 128 + c]);
        }
        colMin[c] = mn;
        colMax[c] = mx;
    } else if (wi == 4) {
        float m = fmaxf(fmaxf(rowMax[lane], rowMax[lane + 32]),
                        fmaxf(rowMax[lane + 64], rowMax[lane + 96]));
        #pragma unroll
        for (int o = 16; o; o >>= 1) m = fmaxf(m, __shfl_xor_sync(FULL, m, o));
        if (lane == 0) misc[0] = 0.1f * m;      // thr = RATIO * max
    }
    __syncthreads();
    const float thr = misc[0];

    // ===== Phase 3: bbox (warp 0 rows, warp 1 cols) =========================
    // lo = 0 iff any index k>=1 has min<thr else 1; hi = max{k>=1 : max>=thr} else 0
    if (wi == 0) {
        bool orB = false; int mx = 0;
        #pragma unroll
        for (int k = lane; k < 128; k += 32) {
            if (k >= 1) {
                if (rowMin[k] <  thr) orB = true;
                if (rowMax[k] >= thr) mx = max(mx, k);
            }
        }
        orB = __any_sync(FULL, orB);
        #pragma unroll
        for (int o = 16; o; o >>= 1) mx = max(mx, __shfl_xor_sync(FULL, mx, o));
        if (lane == 0) { misc[1] = orB ? 0.0f : 1.0f; misc[2] = (float)mx; }
    } else if (wi == 1) {
        bool orB = false; int mx = 0;
        #pragma unroll
        for (int k = lane; k < 128; k += 32) {
            if (k >= 1) {
                if (colMin[k] <  thr) orB = true;
                if (colMax[k] >= thr) mx = max(mx, k);
            }
        }
        orB = __any_sync(FULL, orB);
        #pragma unroll
        for (int o = 16; o; o >>= 1) mx = max(mx, __shfl_xor_sync(FULL, mx, o));
        if (lane == 0) { misc[3] = orB ? 0.0f : 1.0f; misc[4] = (float)mx; }
    }
    __syncthreads();

    // ===== Phase 4: weight + clamped-index tables ===========================
    if (tid < 128) {
        const int  isW = tid >> 6;
        const int  o   = tid & 63;
        const float lo = misc[1 + 2 * isW];
        const float hi = misc[2 + 2 * isW];
        const float L       = hi - lo + 1.0f;
        const float scale   = L * (1.0f / 64.0f);
        const float support = fmaxf(scale, 1.0f);
        const float a       = lo - 0.5f + scale * ((float)o + 0.5f);
        const int   j0      = (int)floorf(a - support);
        float wloc[TAPS]; float ssum = 0.0f;
        #pragma unroll
        for (int k = 0; k < TAPS; k++) {
            const float jf = (float)(j0 + k);
            float wv = fmaxf(0.0f, 1.0f - fabsf(jf - a) / support);
            wv = (jf >= lo && jf <= hi) ? wv : 0.0f;
            wloc[k] = wv; ssum += wv;
        }
        const float inv = 1.0f / fmaxf(ssum, 1e-12f);
        const int base = isW * 384 + o * 6;
        #pragma unroll
        for (int k = 0; k < TAPS; k++) {
            wtab[base + k] = wloc[k] * inv;
            const int j = min(max(j0 + k, 0), 127);        // weight 0 when clamped
            itab[base + k] = isW ? j : j * 32;             // P5: uint2-row offset; P6: element
        }
    }
    __syncthreads();

    // ===== Phase 5: row resize, warp-per-output-row, fp16 in / fp32 out =====
    // tmp[o][w] = sum_k wh[o][k] * xs[jk][w]; lane handles 4 consecutive w.
    #pragma unroll
    for (int o = wi; o < OH; o += NWARPS) {
        const float* wp = wtab + o * 6;
        const int*   ip = itab + o * 6;
        float4 acc = {0.f, 0.f, 0.f, 0.f};
        #pragma unroll
        for (int k = 0; k < TAPS; k++) {
            const float wk = wp[k];
            const uint2 a = xs2[ip[k] + lane];
            const float2 lo2 = __half22float2(*(const __half2*)&a.x);
            const float2 hi2 = __half22float2(*(const __half2*)&a.y);
            acc.x = fmaf(wk, lo2.x, acc.x);
            acc.y = fmaf(wk, lo2.y, acc.y);
            acc.z = fmaf(wk, hi2.x, acc.z);
            acc.w = fmaf(wk, hi2.y, acc.w);
        }
        tmp4[o * 32 + lane] = acc;
    }
    __syncthreads();

    // ===== Phase 6: col resize ==============================================
    // out[o][p] = sum_k ww[p][k] * tmp[o][jk]; thread owns fixed p, 16 o's.
    {
        const int p  = tid & 63;
        const int og = tid >> 6;                 // uniform within a warp
        const float* wp = wtab + 384 + p * 6;
        const int*   ip = itab + 384 + p * 6;
        const float w0 = wp[0], w1 = wp[1], w2 = wp[2],
                    w3 = wp[3], w4 = wp[4], w5 = wp[5];
        const int j0 = ip[0], j1 = ip[1], j2 = ip[2],
                  j3 = ip[3], j4 = ip[4], j5 = ip[5];
        float* outc = out + (size_t)nc * (OH * OW);
        #pragma unroll
        for (int g = 0; g < 16; g++) {
            const int o = og * 16 + g;
            const float* tr = tmp + o * W;
            float acc;
            acc = fmaf(w5, tr[j5], fmaf(w4, tr[j4], fmaf(w3, tr[j3],
                  fmaf(w2, tr[j2], fmaf(w1, tr[j1], w0 * tr[j0])))));
            outc[o * OW + p] = acc;
        }
    }
}

extern "C" void kernel_launch(void* const* d_in, const int* in_sizes, int n_in,
                              void* d_out, int out_size)
{
    const float* x = (const float*)d_in[0];
    float* out = (float*)d_out;
    const int nc = in_sizes[0] / (H * W);   // 4096 channels
    cudaFuncSetAttribute(smartpool_kernel,
                         cudaFuncAttributeMaxDynamicSharedMemorySize, SMEM_BYTES);
    smartpool_kernel<<<nc, NTHREADS, SMEM_BYTES>>>(x, out);
}

// round 12
// speedup vs baseline: 1.8364x; 1.1915x over previous
#include <cuda_runtime.h>
#include <cuda_fp16.h>
#include <cstdint>

#define H 128
#define W 128
#define OH 64
#define OW 64
#define TAPS 6
#define NTHREADS 256
#define NWARPS 8

// SMEM bytes: xs fp16 32768 | tmp fp32 32768 | wtab 3072 | itab 3072 |
//             rowMin 512 | rowMax 512 | misc 32   => 72,736 B  (3 CTAs/SM)
// Aliased onto tmp (dead before Phase 5): partMin[8*128], partMax[8*128],
//             colMin[128], colMax[128] (all fp32)
#define SMEM_BYTES (32768 + 32768 + 3072 + 3072 + 512 + 512 + 32)

// Order-preserving float <-> u32 monotone mapping (radix-sort trick):
// preserves total order on all non-NaN floats.
__device__ __forceinline__ unsigned f2ord(float f) {
    int b = __float_as_int(f);
    return (unsigned)b ^ ((b < 0) ? 0xFFFFFFFFu : 0x80000000u);
}
__device__ __forceinline__ float ord2f(unsigned u) {
    int b = (int)(u ^ ((u & 0x80000000u) ? 0x80000000u : 0xFFFFFFFFu));
    return __int_as_float(b);
}
// Single-MIO-op warp reductions via integer redux (sm_80+; f32 redux needs
// the sm_100a PTX target which this toolchain doesn't emit).
__device__ __forceinline__ unsigned warp_min_u32(unsigned v) {
    unsigned r; asm("redux.sync.min.u32 %0, %1, 0xffffffff;" : "=r"(r) : "r"(v)); return r;
}
__device__ __forceinline__ unsigned warp_max_u32(unsigned v) {
    unsigned r; asm("redux.sync.max.u32 %0, %1, 0xffffffff;" : "=r"(r) : "r"(v)); return r;
}
__device__ __forceinline__ int warp_max_s32(int v) {
    int r; asm("redux.sync.max.s32 %0, %1, 0xffffffff;" : "=r"(r) : "r"(v)); return r;
}
__device__ __forceinline__ float warp_min_f32(float v) { return ord2f(warp_min_u32(f2ord(v))); }
__device__ __forceinline__ float warp_max_f32(float v) { return ord2f(warp_max_u32(f2ord(v))); }

__global__ void __launch_bounds__(NTHREADS, 3)
smartpool_kernel(const float* __restrict__ x, float* __restrict__ out)
{
    extern __shared__ float sm[];
    uint2* xs2    = (uint2*)sm;               // [128 rows][32 uint2] = 4 halfs each
    float* tmp    = sm + 32768/4;             // [64][128] fp32
    float* wtab   = tmp + 8192;               // [2][64][6] weights
    int*   itab   = (int*)(wtab + 768);       // [2][64][6] precomputed indices
    float* rowMin = (float*)(itab + 768);     // [128]
    float* rowMax = rowMin + 128;             // [128]
    float* misc   = rowMax + 128;             // [0]=thr [1..2]=row bbox [3..4]=col bbox
    // aliases on tmp (used only before Phase 5)
    float* partMin = tmp;                     // [8][128]
    float* partMax = tmp + 1024;              // [8][128]
    float* colMin  = tmp + 2048;              // [128]
    float* colMax  = colMin + 128;            // [128]

    const int nc   = blockIdx.x;
    const int tid  = threadIdx.x;
    const int lane = tid & 31;
    const int wi   = tid >> 5;
    const unsigned FULL = 0xFFFFFFFFu;
    const float FINF = 3.402823466e38f;

    const float4* x4 = (const float4*)(x + (size_t)nc * (H * W));
    float4* tmp4 = (float4*)tmp;

    // ===== Phase 1: stream tile -> fp16 SMEM, fused row/col min-max stats ===
    // idx = tid + 256*i -> row r = wi + 8*i (warp covers the full row each iter),
    // lane's float4 covers fixed columns 4*lane..4*lane+3.
    float4 cmn = {FINF, FINF, FINF, FINF};
    float4 cmx = {-FINF, -FINF, -FINF, -FINF};
    #pragma unroll 8
    for (int i = 0; i < 16; i++) {
        const int idx = tid + i * NTHREADS;
        const float4 v = x4[idx];
        // fp16 store (resize input only; stats use exact fp32 below)
        __half2 h01 = __floats2half2_rn(v.x, v.y);
        __half2 h23 = __floats2half2_rn(v.z, v.w);
        uint2 pk;
        pk.x = *(const unsigned*)&h01;
        pk.y = *(const unsigned*)&h23;
        xs2[idx] = pk;
        // column partials (registers, fixed cols per lane)
        cmn.x = fminf(cmn.x, v.x); cmn.y = fminf(cmn.y, v.y);
        cmn.z = fminf(cmn.z, v.z); cmn.w = fminf(cmn.w, v.w);
        cmx.x = fmaxf(cmx.x, v.x); cmx.y = fmaxf(cmx.y, v.y);
        cmx.z = fmaxf(cmx.z, v.z); cmx.w = fmaxf(cmx.w, v.w);
        // row stats: single-op warp reduction (integer redux on ordered bits)
        float lmn = fminf(fminf(v.x, v.y), fminf(v.z, v.w));
        float lmx = fmaxf(fmaxf(v.x, v.y), fmaxf(v.z, v.w));
        lmn = warp_min_f32(lmn);
        lmx = warp_max_f32(lmx);
        if (lane == 0) {
            const int r = wi + 8 * i;
            rowMin[r] = lmn;
            rowMax[r] = lmx;
        }
    }
    ((float4*)partMin)[wi * 32 + lane] = cmn;
    ((float4*)partMax)[wi * 32 + lane] = cmx;
    __syncthreads();

    // ===== Phase 2: finish stats (col reduce tids 0-127, thr warp 4) ========
    if (tid < 128) {
        const int c = tid;
        float mn = partMin[c], mx = partMax[c];
        #pragma unroll
        for (int w = 1; w < 8; w++) {
            mn = fminf(mn, partMin[w * 128 + c]);
            mx = fmaxf(mx, partMax[w * 128 + c]);
        }
        colMin[c] = mn;
        colMax[c] = mx;
    } else if (wi == 4) {
        float m = fmaxf(fmaxf(rowMax[lane], rowMax[lane + 32]),
                        fmaxf(rowMax[lane + 64], rowMax[lane + 96]));
        m = warp_max_f32(m);
        if (lane == 0) misc[0] = 0.1f * m;      // thr = RATIO * max
    }
    __syncthreads();
    const float thr = misc[0];

    // ===== Phase 3: bbox (warp 0 rows, warp 1 cols) =========================
    // lo = 0 iff any index k>=1 has min<thr else 1; hi = max{k>=1 : max>=thr} else 0
    if (wi == 0) {
        bool orB = false; int mx = 0;
        #pragma unroll
        for (int k = lane; k < 128; k += 32) {
            if (k >= 1) {
                if (rowMin[k] <  thr) orB = true;
                if (rowMax[k] >= thr) mx = max(mx, k);
            }
        }
        orB = __any_sync(FULL, orB);
        mx = warp_max_s32(mx);
        if (lane == 0) { misc[1] = orB ? 0.0f : 1.0f; misc[2] = (float)mx; }
    } else if (wi == 1) {
        bool orB = false; int mx = 0;
        #pragma unroll
        for (int k = lane; k < 128; k += 32) {
            if (k >= 1) {
                if (colMin[k] <  thr) orB = true;
                if (colMax[k] >= thr) mx = max(mx, k);
            }
        }
        orB = __any_sync(FULL, orB);
        mx = warp_max_s32(mx);
        if (lane == 0) { misc[3] = orB ? 0.0f : 1.0f; misc[4] = (float)mx; }
    }
    __syncthreads();

    // ===== Phase 4: weight + clamped-index tables ===========================
    if (tid < 128) {
        const int  isW = tid >> 6;
        const int  o   = tid & 63;
        const float lo = misc[1 + 2 * isW];
        const float hi = misc[2 + 2 * isW];
        const float L       = hi - lo + 1.0f;
        const float scale   = L * (1.0f / 64.0f);
        const float support = fmaxf(scale, 1.0f);
        const float a       = lo - 0.5f + scale * ((float)o + 0.5f);
        const int   j0      = (int)floorf(a - support);
        float wloc[TAPS]; float ssum = 0.0f;
        #pragma unroll
        for (int k = 0; k < TAPS; k++) {
            const float jf = (float)(j0 + k);
            float wv = fmaxf(0.0f, 1.0f - fabsf(jf - a) / support);
            wv = (jf >= lo && jf <= hi) ? wv : 0.0f;
            wloc[k] = wv; ssum += wv;
        }
        const float inv = 1.0f / fmaxf(ssum, 1e-12f);
        const int base = isW * 384 + o * 6;
        #pragma unroll
        for (int k = 0; k < TAPS; k++) {
            wtab[base + k] = wloc[k] * inv;
            const int j = min(max(j0 + k, 0), 127);        // weight 0 when clamped
            itab[base + k] = isW ? j : j * 32;             // P5: uint2-row offset; P6: element
        }
    }
    __syncthreads();

    // ===== Phase 5: row resize, warp-per-output-row, fp16 in / fp32 out =====
    // tmp[o][w] = sum_k wh[o][k] * xs[jk][w]; lane handles 4 consecutive w.
    #pragma unroll
    for (int o = wi; o < OH; o += NWARPS) {
        const float* wp = wtab + o * 6;
        const int*   ip = itab + o * 6;
        float4 acc = {0.f, 0.f, 0.f, 0.f};
        #pragma unroll
        for (int k = 0; k < TAPS; k++) {
            const float wk = wp[k];
            const uint2 a = xs2[ip[k] + lane];
            const float2 lo2 = __half22float2(*(const __half2*)&a.x);
            const float2 hi2 = __half22float2(*(const __half2*)&a.y);
            acc.x = fmaf(wk, lo2.x, acc.x);
            acc.y = fmaf(wk, lo2.y, acc.y);
            acc.z = fmaf(wk, hi2.x, acc.z);
            acc.w = fmaf(wk, hi2.y, acc.w);
        }
        tmp4[o * 32 + lane] = acc;
    }
    __syncthreads();

    // ===== Phase 6: col resize, half-warp tap rotation kills bank conflicts =
    // out[o][p] = sum_k ww[p][k] * tmp[o][jk]; thread owns fixed p, 16 o's.
    // Lanes >=16 walk the 6 taps rotated by one slot so the two half-warps hit
    // disjoint bank parities (j ~ 2p => even banks vs odd banks) per LDS issue.
    {
        const int p   = tid & 63;
        const int og  = tid >> 6;                // uniform within a warp
        const int rot = (lane >> 4) & 1;         // 0 for lanes 0-15, 1 for 16-31
        const float* wp = wtab + 384 + p * 6;
        const int*   ip = itab + 384 + p * 6;
        float wr[TAPS]; int jr[TAPS];
        #pragma unroll
        for (int k = 0; k < TAPS; k++) {
            int kk = k + rot; kk = (kk == TAPS) ? 0 : kk;
            wr[k] = wp[kk];
            jr[k] = ip[kk];
        }
        float* outc = out + (size_t)nc * (OH * OW);
        #pragma unroll
        for (int g = 0; g < 16; g++) {
            const int o = og * 16 + g;
            const float* tr = tmp + o * W;
            float acc;
            acc = fmaf(wr[5], tr[jr[5]], fmaf(wr[4], tr[jr[4]], fmaf(wr[3], tr[jr[3]],
                  fmaf(wr[2], tr[jr[2]], fmaf(wr[1], tr[jr[1]], wr[0] * tr[jr[0]])))));
            outc[o * OW + p] = acc;
        }
    }
}

extern "C" void kernel_launch(void* const* d_in, const int* in_sizes, int n_in,
                              void* d_out, int out_size)
{
    const float* x = (const float*)d_in[0];
    float* out = (float*)d_out;
    const int nc = in_sizes[0] / (H * W);   // 4096 channels
    cudaFuncSetAttribute(smartpool_kernel,
                         cudaFuncAttributeMaxDynamicSharedMemorySize, SMEM_BYTES);
    smartpool_kernel<<<nc, NTHREADS, SMEM_BYTES>>>(x, out);
}

// round 13
// speedup vs baseline: 2.1052x; 1.1463x over previous
#include <cuda_runtime.h>
#include <cuda_fp16.h>
#include <cstdint>

#define H 128
#define W 128
#define OH 64
#define OW 64
#define TAPS 6
#define NTHREADS 256
#define NWARPS 8

// Byte layout (56,624 B total => 4 CTAs/SM on sm_100a):
//   0      xs2      fp16 tile          32768
//   32768  tmp16    fp16 [64][136]     17408   (4+128+4 guard halfs per row)
//   50176  wtab     P5 weights 64x6    1536
//   51712  wtab8    P6 weights 64x8    2048    (window-aligned, zero-padded)
//   53760  itabP5   64x6 row offsets   1536
//   55296  word0tab 64 ints            256
//   55552  rowMinOrd u32[128]          512
//   56064  rowMaxOrd u32[128]          512
//   56576  misc                        48
// Aliased on tmp16 (dead before P5): partMin f32[1024], partMax f32[1024],
//   colMin f32[128], colMax f32[128]  (9216 B <= 17408)
#define SMEM_BYTES 56624

// Order-preserving float <-> u32 monotone mapping (exact on all non-NaN).
__device__ __forceinline__ unsigned f2ord(float f) {
    int b = __float_as_int(f);
    return (unsigned)b ^ ((b < 0) ? 0xFFFFFFFFu : 0x80000000u);
}
__device__ __forceinline__ float ord2f(unsigned u) {
    int b = (int)(u ^ ((u & 0x80000000u) ? 0x80000000u : 0xFFFFFFFFu));
    return __int_as_float(b);
}
__device__ __forceinline__ unsigned warp_min_u32(unsigned v) {
    unsigned r; asm("redux.sync.min.u32 %0, %1, 0xffffffff;" : "=r"(r) : "r"(v)); return r;
}
__device__ __forceinline__ unsigned warp_max_u32(unsigned v) {
    unsigned r; asm("redux.sync.max.u32 %0, %1, 0xffffffff;" : "=r"(r) : "r"(v)); return r;
}
__device__ __forceinline__ int warp_max_s32(int v) {
    int r; asm("redux.sync.max.s32 %0, %1, 0xffffffff;" : "=r"(r) : "r"(v)); return r;
}

__global__ void __launch_bounds__(NTHREADS, 4)
smartpool_kernel(const float* __restrict__ x, float* __restrict__ out)
{
    extern __shared__ char smc[];
    uint2*    xs2      = (uint2*)smc;                   // 128 rows x 32 uint2 (4 halfs)
    __half*   tmp16    = (__half*)(smc + 32768);        // [64][136]
    float*    wtab     = (float*)(smc + 50176);         // [64][6]
    float*    wtab8    = (float*)(smc + 51712);         // [64][8]
    int*      itabP5   = (int*)(smc + 53760);           // [64][6]
    int*      word0tab = (int*)(smc + 55296);           // [64]
    unsigned* rowMinOrd= (unsigned*)(smc + 55552);      // [128]
    unsigned* rowMaxOrd= (unsigned*)(smc + 56064);      // [128]
    float*    misc     = (float*)(smc + 56576);         // [0]=thr f32, u[1]=thrOrd, [2..5]=bbox
    unsigned* miscU    = (unsigned*)misc;
    // aliases on tmp16 (used only before Phase 5)
    float* partMin = (float*)tmp16;                     // [8][128]
    float* partMax = partMin + 1024;
    float* colMin  = partMin + 2048;                    // [128]
    float* colMax  = colMin + 128;

    const int nc   = blockIdx.x;
    const int tid  = threadIdx.x;
    const int lane = tid & 31;
    const int wi   = tid >> 5;
    const unsigned FULL = 0xFFFFFFFFu;
    const float FINF = 3.402823466e38f;

    const float4* x4 = (const float4*)(x + (size_t)nc * (H * W));

    // ===== Phase 1: stream tile -> fp16 SMEM, fused row/col min-max stats ===
    float4 cmn = {FINF, FINF, FINF, FINF};
    float4 cmx = {-FINF, -FINF, -FINF, -FINF};
    #pragma unroll 8
    for (int i = 0; i < 16; i++) {
        const int idx = tid + i * NTHREADS;
        const float4 v = x4[idx];
        __half2 h01 = __floats2half2_rn(v.x, v.y);
        __half2 h23 = __floats2half2_rn(v.z, v.w);
        uint2 pk;
        pk.x = *(const unsigned*)&h01;
        pk.y = *(const unsigned*)&h23;
        xs2[idx] = pk;
        cmn.x = fminf(cmn.x, v.x); cmn.y = fminf(cmn.y, v.y);
        cmn.z = fminf(cmn.z, v.z); cmn.w = fminf(cmn.w, v.w);
        cmx.x = fmaxf(cmx.x, v.x); cmx.y = fmaxf(cmx.y, v.y);
        cmx.z = fmaxf(cmx.z, v.z); cmx.w = fmaxf(cmx.w, v.w);
        // row stats: warp covers the full row; reduce in ordered-u32 domain
        float lmn = fminf(fminf(v.x, v.y), fminf(v.z, v.w));
        float lmx = fmaxf(fmaxf(v.x, v.y), fmaxf(v.z, v.w));
        unsigned omn = warp_min_u32(f2ord(lmn));
        unsigned omx = warp_max_u32(f2ord(lmx));
        if (lane == 0) {
            const int r = wi + 8 * i;
            rowMinOrd[r] = omn;
            rowMaxOrd[r] = omx;
        }
    }
    ((float4*)partMin)[wi * 32 + lane] = cmn;
    ((float4*)partMax)[wi * 32 + lane] = cmx;
    __syncthreads();

    // ===== Phase 2: finish stats (col reduce tids 0-127, thr warp 4) ========
    if (tid < 128) {
        const int c = tid;
        float mn = partMin[c], mx = partMax[c];
        #pragma unroll
        for (int w = 1; w < 8; w++) {
            mn = fminf(mn, partMin[w * 128 + c]);
            mx = fmaxf(mx, partMax[w * 128 + c]);
        }
        colMin[c] = mn;
        colMax[c] = mx;
    } else if (wi == 4) {
        unsigned m = max(max(rowMaxOrd[lane], rowMaxOrd[lane + 32]),
                         max(rowMaxOrd[lane + 64], rowMaxOrd[lane + 96]));
        m = warp_max_u32(m);
        if (lane == 0) {
            const float thr = 0.1f * ord2f(m);
            misc[0]  = thr;
            miscU[1] = f2ord(thr);
        }
    }
    __syncthreads();

    // ===== Phase 3: bbox (warp 0 rows in u32 domain, warp 1 cols in f32) ====
    if (wi == 0) {
        const unsigned thrO = miscU[1];
        bool orB = false; int mx = 0;
        #pragma unroll
        for (int k = lane; k < 128; k += 32) {
            if (k >= 1) {
                if (rowMinOrd[k] <  thrO) orB = true;
                if (rowMaxOrd[k] >= thrO) mx = max(mx, k);
            }
        }
        orB = __any_sync(FULL, orB);
        mx = warp_max_s32(mx);
        if (lane == 0) { misc[2] = orB ? 0.0f : 1.0f; misc[3] = (float)mx; }
    } else if (wi == 1) {
        const float thr = misc[0];
        bool orB = false; int mx = 0;
        #pragma unroll
        for (int k = lane; k < 128; k += 32) {
            if (k >= 1) {
                if (colMin[k] <  thr) orB = true;
                if (colMax[k] >= thr) mx = max(mx, k);
            }
        }
        orB = __any_sync(FULL, orB);
        mx = warp_max_s32(mx);
        if (lane == 0) { misc[4] = orB ? 0.0f : 1.0f; misc[5] = (float)mx; }
    }
    __syncthreads();

    // ===== Phase 4: weight tables (tid<128) + tmp guard zeroing (tid>=128) ==
    if (tid < 128) {
        const int  isW = tid >> 6;
        const int  o   = tid & 63;
        const float lo = misc[2 + 2 * isW];
        const float hi = misc[3 + 2 * isW];
        const float L       = hi - lo + 1.0f;
        const float scale   = L * (1.0f / 64.0f);
        const float support = fmaxf(scale, 1.0f);
        const float a       = lo - 0.5f + scale * ((float)o + 0.5f);
        const int   j0      = (int)floorf(a - support);     // proven in [-2,125]
        float wloc[TAPS]; float ssum = 0.0f;
        #pragma unroll
        for (int k = 0; k < TAPS; k++) {
            const float jf = (float)(j0 + k);
            float wv = fmaxf(0.0f, 1.0f - fabsf(jf - a) / support);
            wv = (jf >= lo && jf <= hi) ? wv : 0.0f;
            wloc[k] = wv; ssum += wv;
        }
        const float inv = 1.0f / fmaxf(ssum, 1e-12f);
        if (isW == 0) {
            #pragma unroll
            for (int k = 0; k < TAPS; k++) {
                wtab[o * 6 + k] = wloc[k] * inv;
                itabP5[o * 6 + k] = min(max(j0 + k, 0), 127) * 32;  // uint2-row offset
            }
        } else {
            // P6: window-aligned 8-slot weights; guards carry weight 0
            const int jb4   = j0 + 4;           // guard-shifted, in [2,129]
            const int word0 = jb4 >> 1;
            const int off   = jb4 & 1;
            float w8[8];
            #pragma unroll
            for (int k = 0; k < 8; k++) w8[k] = 0.0f;
            #pragma unroll
            for (int k = 0; k < TAPS; k++) w8[off + k] = wloc[k] * inv;
            #pragma unroll
            for (int k = 0; k < 8; k++) wtab8[o * 8 + k] = w8[k];
            word0tab[o] = word0;
        }
    } else {
        // zero the 4 guard words per tmp16 row (words 0,1,66,67 of 68)
        const int t = tid - 128;               // 0..127
        const int r = t >> 1;                  // row 0..63
        const int base = r * 68 + ((t & 1) ? 66 : 0);
        ((unsigned*)tmp16)[base]     = 0u;
        ((unsigned*)tmp16)[base + 1] = 0u;
    }
    __syncthreads();

    // ===== Phase 5: row resize, warp-per-output-row, fp16 in / fp16 out =====
    uint2* tmp2 = (uint2*)tmp16;               // row stride 34 uint2
    #pragma unroll 2
    for (int o = wi; o < OH; o += NWARPS) {
        const float* wp = wtab + o * 6;
        const int*   ip = itabP5 + o * 6;
        float4 acc = {0.f, 0.f, 0.f, 0.f};
        #pragma unroll
        for (int k = 0; k < TAPS; k++) {
            const float wk = wp[k];
            const uint2 a = xs2[ip[k] + lane];
            const float2 lo2 = __half22float2(*(const __half2*)&a.x);
            const float2 hi2 = __half22float2(*(const __half2*)&a.y);
            acc.x = fmaf(wk, lo2.x, acc.x);
            acc.y = fmaf(wk, lo2.y, acc.y);
            acc.z = fmaf(wk, hi2.x, acc.z);
            acc.w = fmaf(wk, hi2.y, acc.w);
        }
        __half2 p01 = __floats2half2_rn(acc.x, acc.y);
        __half2 p23 = __floats2half2_rn(acc.z, acc.w);
        uint2 pk;
        pk.x = *(const unsigned*)&p01;
        pk.y = *(const unsigned*)&p23;
        tmp2[o * 34 + 1 + lane] = pk;          // halfs 4+4*lane .. 7+4*lane
    }
    __syncthreads();

    // ===== Phase 6: col resize from guarded fp16 tmp, 4xLDS.32 + 8 FMA ======
    {
        const int p  = tid & 63;
        const int og = tid >> 6;
        const unsigned* t32 = (const unsigned*)tmp16;
        float w8[8];
        #pragma unroll
        for (int k = 0; k < 8; k++) w8[k] = wtab8[p * 8 + k];
        const int word0 = word0tab[p];
        float* outc = out + (size_t)nc * (OH * OW);
        #pragma unroll 4
        for (int g = 0; g < 16; g++) {
            const int o = og * 16 + g;
            const int base = o * 68 + word0;
            const unsigned u0 = t32[base + 0];
            const unsigned u1 = t32[base + 1];
            const unsigned u2 = t32[base + 2];
            const unsigned u3 = t32[base + 3];
            const float2 f0 = __half22float2(*(const __half2*)&u0);
            const float2 f1 = __half22float2(*(const __half2*)&u1);
            const float2 f2 = __half22float2(*(const __half2*)&u2);
            const float2 f3 = __half22float2(*(const __half2*)&u3);
            float acc;
            acc =      w8[0] * f0.x;
            acc = fmaf(w8[1], f0.y, acc);
            acc = fmaf(w8[2], f1.x, acc);
            acc = fmaf(w8[3], f1.y, acc);
            acc = fmaf(w8[4], f2.x, acc);
            acc = fmaf(w8[5], f2.y, acc);
            acc = fmaf(w8[6], f3.x, acc);
            acc = fmaf(w8[7], f3.y, acc);
            outc[o * OW + p] = acc;
        }
    }
}

extern "C" void kernel_launch(void* const* d_in, const int* in_sizes, int n_in,
                              void* d_out, int out_size)
{
    const float* x = (const float*)d_in[0];
    float* out = (float*)d_out;
    const int nc = in_sizes[0] / (H * W);   // 4096 channels
    cudaFuncSetAttribute(smartpool_kernel,
                         cudaFuncAttributeMaxDynamicSharedMemorySize, SMEM_BYTES);
    smartpool_kernel<<<nc, NTHREADS, SMEM_BYTES>>>(x, out);
}

// round 15
// speedup vs baseline: 2.1536x; 1.0230x over previous
#include <cuda_runtime.h>
#include <cuda_fp16.h>
#include <cstdint>

#define H 128
#define W 128
#define OH 64
#define OW 64
#define TAPS 6
#define NTHREADS 256
#define NWARPS 8

// Byte layout (56,624 B total => 4 CTAs/SM):
//   0      xs2      fp16 tile          32768
//   32768  tmp16    fp16 [64][136]     17408   (4+128+4 guard halfs per row)
//   50176  wtab16h  P5 half2 wts 64x6  1536    (uint-packed {w,w})
//   51712  wtab8    P6 weights 64x8    2048    (window-aligned, zero-padded)
//   53760  itabP5   64x6 row offsets   1536    (uint4-row units)
//   55296  word0tab 64 ints            256
//   55552  rowMinOrd u32[128]          512
//   56064  rowMaxOrd u32[128]          512
//   56576  misc                        48
// Aliased on tmp16 (dead before P5): partMin f32[1024], partMax f32[1024],
//   colMin f32[128], colMax f32[128]
#define SMEM_BYTES 56624

__device__ __forceinline__ unsigned f2ord(float f) {
    int b = __float_as_int(f);
    return (unsigned)b ^ ((b < 0) ? 0xFFFFFFFFu : 0x80000000u);
}
__device__ __forceinline__ float ord2f(unsigned u) {
    int b = (int)(u ^ ((u & 0x80000000u) ? 0x80000000u : 0xFFFFFFFFu));
    return __int_as_float(b);
}
__device__ __forceinline__ unsigned warp_min_u32(unsigned v) {
    unsigned r; asm("redux.sync.min.u32 %0, %1, 0xffffffff;" : "=r"(r) : "r"(v)); return r;
}
__device__ __forceinline__ unsigned warp_max_u32(unsigned v) {
    unsigned r; asm("redux.sync.max.u32 %0, %1, 0xffffffff;" : "=r"(r) : "r"(v)); return r;
}
__device__ __forceinline__ int warp_max_s32(int v) {
    int r; asm("redux.sync.max.s32 %0, %1, 0xffffffff;" : "=r"(r) : "r"(v)); return r;
}

__global__ void __launch_bounds__(NTHREADS, 4)
smartpool_kernel(const float* __restrict__ x, float* __restrict__ out)
{
    extern __shared__ char smc[];
    uint2*    xs2      = (uint2*)smc;                   // 128 rows x 32 uint2
    __half*   tmp16    = (__half*)(smc + 32768);        // [64][136]
    unsigned* wtab16h  = (unsigned*)(smc + 50176);      // [64][6] packed half2 {w,w}
    float*    wtab8    = (float*)(smc + 51712);         // [64][8]
    int*      itabP5   = (int*)(smc + 53760);           // [64][6]
    int*      word0tab = (int*)(smc + 55296);           // [64]
    unsigned* rowMinOrd= (unsigned*)(smc + 55552);      // [128]
    unsigned* rowMaxOrd= (unsigned*)(smc + 56064);      // [128]
    float*    misc     = (float*)(smc + 56576);
    unsigned* miscU    = (unsigned*)misc;
    float* partMin = (float*)tmp16;                     // aliases, dead before P5
    float* partMax = partMin + 1024;
    float* colMin  = partMin + 2048;
    float* colMax  = colMin + 128;

    const int nc   = blockIdx.x;
    const int tid  = threadIdx.x;
    const int lane = tid & 31;
    const int wi   = tid >> 5;
    const unsigned FULL = 0xFFFFFFFFu;
    const float FINF = 3.402823466e38f;

    const float4* x4 = (const float4*)(x + (size_t)nc * (H * W));

    // ===== Phase 1: stream tile -> fp16 SMEM, fused row/col min-max stats ===
    float4 cmn = {FINF, FINF, FINF, FINF};
    float4 cmx = {-FINF, -FINF, -FINF, -FINF};
    #pragma unroll 8
    for (int i = 0; i < 16; i++) {
        const int idx = tid + i * NTHREADS;
        const float4 v = x4[idx];
        __half2 h01 = __floats2half2_rn(v.x, v.y);
        __half2 h23 = __floats2half2_rn(v.z, v.w);
        uint2 pk;
        pk.x = *(const unsigned*)&h01;
        pk.y = *(const unsigned*)&h23;
        xs2[idx] = pk;
        cmn.x = fminf(cmn.x, v.x); cmn.y = fminf(cmn.y, v.y);
        cmn.z = fminf(cmn.z, v.z); cmn.w = fminf(cmn.w, v.w);
        cmx.x = fmaxf(cmx.x, v.x); cmx.y = fmaxf(cmx.y, v.y);
        cmx.z = fmaxf(cmx.z, v.z); cmx.w = fmaxf(cmx.w, v.w);
        float lmn = fminf(fminf(v.x, v.y), fminf(v.z, v.w));
        float lmx = fmaxf(fmaxf(v.x, v.y), fmaxf(v.z, v.w));
        unsigned omn = warp_min_u32(f2ord(lmn));
        unsigned omx = warp_max_u32(f2ord(lmx));
        if (lane == 0) {
            const int r = wi + 8 * i;
            rowMinOrd[r] = omn;
            rowMaxOrd[r] = omx;
        }
    }
    ((float4*)partMin)[wi * 32 + lane] = cmn;
    ((float4*)partMax)[wi * 32 + lane] = cmx;
    __syncthreads();

    // ===== Phase 2: finish stats (col reduce tids 0-127, thr warp 4) ========
    if (tid < 128) {
        const int c = tid;
        float mn = partMin[c], mx = partMax[c];
        #pragma unroll
        for (int w = 1; w < 8; w++) {
            mn = fminf(mn, partMin[w * 128 + c]);
            mx = fmaxf(mx, partMax[w * 128 + c]);
        }
        colMin[c] = mn;
        colMax[c] = mx;
    } else if (wi == 4) {
        unsigned m = max(max(rowMaxOrd[lane], rowMaxOrd[lane + 32]),
                         max(rowMaxOrd[lane + 64], rowMaxOrd[lane + 96]));
        m = warp_max_u32(m);
        if (lane == 0) {
            const float thr = 0.1f * ord2f(m);
            misc[0]  = thr;
            miscU[1] = f2ord(thr);
        }
    }
    __syncthreads();

    // ===== Phase 3: bbox (warp 0 rows in u32 domain, warp 1 cols in f32) ====
    if (wi == 0) {
        const unsigned thrO = miscU[1];
        bool orB = false; int mx = 0;
        #pragma unroll
        for (int k = lane; k < 128; k += 32) {
            if (k >= 1) {
                if (rowMinOrd[k] <  thrO) orB = true;
                if (rowMaxOrd[k] >= thrO) mx = max(mx, k);
            }
        }
        orB = __any_sync(FULL, orB);
        mx = warp_max_s32(mx);
        if (lane == 0) { misc[2] = orB ? 0.0f : 1.0f; misc[3] = (float)mx; }
    } else if (wi == 1) {
        const float thr = misc[0];
        bool orB = false; int mx = 0;
        #pragma unroll
        for (int k = lane; k < 128; k += 32) {
            if (k >= 1) {
                if (colMin[k] <  thr) orB = true;
                if (colMax[k] >= thr) mx = max(mx, k);
            }
        }
        orB = __any_sync(FULL, orB);
        mx = warp_max_s32(mx);
        if (lane == 0) { misc[4] = orB ? 0.0f : 1.0f; misc[5] = (float)mx; }
    }
    __syncthreads();

    // ===== Phase 4: weight tables (tid<128) + tmp guard zeroing (tid>=128) ==
    if (tid < 128) {
        const int  isW = tid >> 6;
        const int  o   = tid & 63;
        const float lo = misc[2 + 2 * isW];
        const float hi = misc[3 + 2 * isW];
        const float L       = hi - lo + 1.0f;
        const float scale   = L * (1.0f / 64.0f);
        const float support = fmaxf(scale, 1.0f);
        const float a       = lo - 0.5f + scale * ((float)o + 0.5f);
        const int   j0      = (int)floorf(a - support);     // in [-2,125]
        float wloc[TAPS]; float ssum = 0.0f;
        #pragma unroll
        for (int k = 0; k < TAPS; k++) {
            const float jf = (float)(j0 + k);
            float wv = fmaxf(0.0f, 1.0f - fabsf(jf - a) / support);
            wv = (jf >= lo && jf <= hi) ? wv : 0.0f;
            wloc[k] = wv; ssum += wv;
        }
        const float inv = 1.0f / fmaxf(ssum, 1e-12f);
        if (isW == 0) {
            #pragma unroll
            for (int k = 0; k < TAPS; k++) {
                const __half2 wh2 = __half2half2(__float2half_rn(wloc[k] * inv));
                wtab16h[o * 6 + k] = *(const unsigned*)&wh2;
                itabP5[o * 6 + k] = min(max(j0 + k, 0), 127) * 16;  // uint4-row offset
            }
        } else {
            const int jb4   = j0 + 4;           // guard-shifted, in [2,129]
            const int word0 = jb4 >> 1;
            const int off   = jb4 & 1;
            float w8[8];
            #pragma unroll
            for (int k = 0; k < 8; k++) w8[k] = 0.0f;
            #pragma unroll
            for (int k = 0; k < TAPS; k++) w8[off + k] = wloc[k] * inv;
            #pragma unroll
            for (int k = 0; k < 8; k++) wtab8[o * 8 + k] = w8[k];
            word0tab[o] = word0;
        }
    } else {
        const int t = tid - 128;
        const int r = t >> 1;
        const int base = r * 68 + ((t & 1) ? 66 : 0);
        ((unsigned*)tmp16)[base]     = 0u;
        ((unsigned*)tmp16)[base + 1] = 0u;
    }
    __syncthreads();

    // ===== Phase 5: row resize, all-half2 (HFMA2), LDS.128, 2 rows/warp-iter =
    // o = wi*8 + 2t + (lane>>4); lane&15 covers 8 cols (uint4 = 4 half2).
    {
        const uint4* xs4 = (const uint4*)smc;      // row stride 16 uint4
        uint2* tmp2 = (uint2*)tmp16;               // row stride 34 uint2
        const int h = lane >> 4;
        const int c = lane & 15;
        #pragma unroll
        for (int t = 0; t < 4; t++) {
            const int o = wi * 8 + 2 * t + h;
            const unsigned* wp = wtab16h + o * 6;
            const int*      ip = itabP5  + o * 6;
            __half2 acc0 = __float2half2_rn(0.0f);
            __half2 acc1 = acc0, acc2 = acc0, acc3 = acc0;
            #pragma unroll
            for (int k = 0; k < TAPS; k++) {
                const unsigned wb = wp[k];
                const __half2 wk = *(const __half2*)&wb;
                const uint4 v = xs4[ip[k] + c];
                acc0 = __hfma2(*(const __half2*)&v.x, wk, acc0);
                acc1 = __hfma2(*(const __half2*)&v.y, wk, acc1);
                acc2 = __hfma2(*(const __half2*)&v.z, wk, acc2);
                acc3 = __hfma2(*(const __half2*)&v.w, wk, acc3);
            }
            uint2 p0, p1;
            p0.x = *(const unsigned*)&acc0;
            p0.y = *(const unsigned*)&acc1;
            p1.x = *(const unsigned*)&acc2;
            p1.y = *(const unsigned*)&acc3;
            tmp2[o * 34 + 1 + 2 * c] = p0;         // halfs 4+8c .. 7+8c
            tmp2[o * 34 + 2 + 2 * c] = p1;         // halfs 8+8c .. 11+8c
        }
    }
    __syncthreads();

    // ===== Phase 6: col resize from guarded fp16 tmp, 4xLDS.32 + 8 FMA ======
    {
        const int p  = tid & 63;
        const int og = tid >> 6;
        const unsigned* t32 = (const unsigned*)tmp16;
        float w8[8];
        #pragma unroll
        for (int k = 0; k < 8; k++) w8[k] = wtab8[p * 8 + k];
        const int word0 = word0tab[p];
        float* outc = out + (size_t)nc * (OH * OW);
        #pragma unroll 4
        for (int g = 0; g < 16; g++) {
            const int o = og * 16 + g;
            const int base = o * 68 + word0;
            const unsigned u0 = t32[base + 0];
            const unsigned u1 = t32[base + 1];
            const unsigned u2 = t32[base + 2];
            const unsigned u3 = t32[base + 3];
            const float2 f0 = __half22float2(*(const __half2*)&u0);
            const float2 f1 = __half22float2(*(const __half2*)&u1);
            const float2 f2 = __half22float2(*(const __half2*)&u2);
            const float2 f3 = __half22float2(*(const __half2*)&u3);
            float acc;
            acc =      w8[0] * f0.x;
            acc = fmaf(w8[1], f0.y, acc);
            acc = fmaf(w8[2], f1.x, acc);
            acc = fmaf(w8[3], f1.y, acc);
            acc = fmaf(w8[4], f2.x, acc);
            acc = fmaf(w8[5], f2.y, acc);
            acc = fmaf(w8[6], f3.x, acc);
            acc = fmaf(w8[7], f3.y, acc);
            outc[o * OW + p] = acc;
        }
    }
}

extern "C" void kernel_launch(void* const* d_in, const int* in_sizes, int n_in,
                              void* d_out, int out_size)
{
    const float* x = (const float*)d_in[0];
    float* out = (float*)d_out;
    const int nc = in_sizes[0] / (H * W);   // 4096 channels
    cudaFuncSetAttribute(smartpool_kernel,
                         cudaFuncAttributeMaxDynamicSharedMemorySize, SMEM_BYTES);
    smartpool_kernel<<<nc, NTHREADS, SMEM_BYTES>>>(x, out);
}